// round 16
// baseline (speedup 1.0000x reference)
#include <cuda_runtime.h>
#include <cuda_bf16.h>
#include <math.h>
#include <stdint.h>

#define NTOK 16384          // BATCH * SEQ
#define SEQL 2048
#define NB   8
#define DM   384
#define DI   768
#define DS   16
#define DTR  24
#define XD   56             // DTR + 2*DS
#define XZW  1536           // 2*DI

// ---------------- scratch (static device memory; no allocation) ------------
__device__ __align__(16) float g_xs  [(size_t)NTOK * DI];
__device__ __align__(16) float g_xdbl[(size_t)NTOK * XD];
__device__ __align__(16) float g_dt  [(size_t)NTOK * DI];
__device__ __align__(16) float g_y   [(size_t)NTOK * DI];
__device__ __align__(16) float g_h2  [(size_t)NTOK * DM];

// bf16 tensors
__device__ __align__(16) __nv_bfloat16 g_xzb  [(size_t)NTOK * XZW];
__device__ __align__(16) __nv_bfloat16 g_xnb  [(size_t)NTOK * DM];
__device__ __align__(16) __nv_bfloat16 g_xsb  [(size_t)NTOK * DI];
__device__ __align__(16) __nv_bfloat16 g_xdblb[(size_t)NTOK * XD];
__device__ __align__(16) __nv_bfloat16 g_yb   [(size_t)NTOK * DI];
// bf16 weights
#define W_INP  ((size_t)2 * XZW * DM)
#define W_XP   ((size_t)2 * XD * DI)
#define W_DTW  ((size_t)2 * DI * DTR)
#define W_OUTP ((size_t)2 * DM * DI)
__device__ __align__(16) __nv_bfloat16 g_w_inp [W_INP];
__device__ __align__(16) __nv_bfloat16 g_w_xp  [W_XP];
__device__ __align__(16) __nv_bfloat16 g_w_dtw [W_DTW];
__device__ __align__(16) __nv_bfloat16 g_w_outp[W_OUTP];

// ---------------- fp32 -> bf16 conversion (vectorized) ----------------------
__global__ void cvt4_kernel(const float4* __restrict__ src,
                            __nv_bfloat162* __restrict__ dst, int n4)
{
    int i = blockIdx.x * blockDim.x + threadIdx.x;
    if (i >= n4) return;
    float4 v = src[i];
    dst[2 * i + 0] = __floats2bfloat162_rn(v.x, v.y);
    dst[2 * i + 1] = __floats2bfloat162_rn(v.z, v.w);
}

// ------- x_proj cvt with B/C row interleave ---------------------------------
__global__ void cvt_xp_kernel(const float* __restrict__ src,
                              __nv_bfloat16* __restrict__ dst)
{
    int i = blockIdx.x * blockDim.x + threadIdx.x;   // over 2*XD*DI
    if (i >= 2 * XD * DI) return;
    int layer = i / (XD * DI);
    int rem   = i - layer * XD * DI;
    int row   = rem / DI;
    int col   = rem - row * DI;
    int srow;
    if (row < DTR)             srow = row;
    else {
        int t = row - DTR;     // 0..31
        srow = (t & 1) ? (DTR + DS + (t >> 1)) : (DTR + (t >> 1));
    }
    dst[i] = __float2bfloat16_rn(src[(size_t)layer * XD * DI
                                     + (size_t)srow * DI + col]);
}

// ---------------- layernorm: one block per token, bf16 output --------------
__global__ void ln_kernel(const float* __restrict__ in,
                          const float* __restrict__ w,
                          const float* __restrict__ b,
                          __nv_bfloat16* __restrict__ out)
{
    int row = blockIdx.x;
    const float* x = in + (size_t)row * DM;
    int t = threadIdx.x;
    float v[3];
    float s = 0.f;
    #pragma unroll
    for (int i = 0; i < 3; i++) { v[i] = x[t + i * 128]; s += v[i]; }

    __shared__ float red[4];
    #pragma unroll
    for (int o = 16; o > 0; o >>= 1) s += __shfl_xor_sync(0xffffffffu, s, o);
    if ((t & 31) == 0) red[t >> 5] = s;
    __syncthreads();
    float mu = (red[0] + red[1] + red[2] + red[3]) * (1.f / 384.f);

    float q = 0.f;
    #pragma unroll
    for (int i = 0; i < 3; i++) { float d = v[i] - mu; q = fmaf(d, d, q); }
    #pragma unroll
    for (int o = 16; o > 0; o >>= 1) q += __shfl_xor_sync(0xffffffffu, q, o);
    __syncthreads();
    if ((t & 31) == 0) red[t >> 5] = q;
    __syncthreads();
    float var = (red[0] + red[1] + red[2] + red[3]) * (1.f / 384.f);
    float rs = rsqrtf(var + 1e-5f);

    __nv_bfloat16* o = out + (size_t)row * DM;
    #pragma unroll
    for (int i = 0; i < 3; i++) {
        int c = t + i * 128;
        o[c] = __float2bfloat16_rn((v[i] - mu) * rs * w[c] + b[c]);
    }
}

// ================= BF16 tensor-core NT GEMM (ldmatrix mainloop) =============
#define TBM 128
#define TBN 128
#define TBK 32
#define HSTRIDE 40
#define TBUFH (TBM * HSTRIDE)

__device__ __forceinline__ void cp_async16(uint32_t dst, const void* src, bool ok)
{
    int sz = ok ? 16 : 0;
    asm volatile("cp.async.cg.shared.global [%0], [%1], 16, %2;\n"
                 :: "r"(dst), "l"(src), "r"(sz));
}
__device__ __forceinline__ void cp_commit() {
    asm volatile("cp.async.commit_group;\n");
}
__device__ __forceinline__ void cp_wait1() {
    asm volatile("cp.async.wait_group 1;\n");
}
__device__ __forceinline__ void ldsm_x4(uint32_t addr, uint32_t& r0, uint32_t& r1,
                                        uint32_t& r2, uint32_t& r3)
{
    asm volatile("ldmatrix.sync.aligned.m8n8.x4.shared.b16 {%0,%1,%2,%3}, [%4];\n"
                 : "=r"(r0), "=r"(r1), "=r"(r2), "=r"(r3) : "r"(addr));
}

// epi: 0 = none, 1 = softplus(v + bias[n]),
//      2 = v + resid[m*ldr+n], stored with sequence flip (row ^ 2047)
__global__ void __launch_bounds__(256, 2)
gemm_bf16(const __nv_bfloat16* __restrict__ A, int lda,
          const __nv_bfloat16* __restrict__ B, int ldb,
          float* __restrict__ C, int ldc,
          __nv_bfloat16* __restrict__ Cb,
          const float* __restrict__ bias,
          const float* __restrict__ resid, int ldr,
          int M, int N, int K, int epi)
{
    extern __shared__ __nv_bfloat16 smem[];
    __nv_bfloat16* AsB = smem;
    __nv_bfloat16* BsB = smem + 2 * TBUFH;

    int tid  = threadIdx.x;
    int lane = tid & 31;
    int warp = tid >> 5;
    int gid  = lane >> 2;
    int tig  = lane & 3;
    int wm   = (warp >> 2) * 64;
    int wn   = (warp & 3) * 32;

    int m0 = blockIdx.y * TBM;
    int n0 = blockIdx.x * TBN;
    int nc = (K + TBK - 1) / TBK;

    uint32_t smem_u = (uint32_t)__cvta_generic_to_shared(smem);

    int ar = lane & 15, ahi = lane >> 4;
    uint32_t aBase = smem_u + (uint32_t)((wm + ar) * 80 + ahi * 16);
    int bq = lane >> 3;
    uint32_t bBase = smem_u + (uint32_t)(2 * TBUFH * 2)
                   + (uint32_t)((wn + (bq >> 1) * 8 + (lane & 7)) * 80
                                + (bq & 1) * 16);

    float acc[4][4][4];
    #pragma unroll
    for (int i = 0; i < 4; i++)
        #pragma unroll
        for (int j = 0; j < 4; j++)
            #pragma unroll
            for (int c = 0; c < 4; c++) acc[i][j][c] = 0.f;

    auto load_tiles = [&](int buf, int chunk) {
        int k0 = chunk * TBK;
        __nv_bfloat16* Asb = AsB + buf * TBUFH;
        __nv_bfloat16* Bsb = BsB + buf * TBUFH;
        #pragma unroll
        for (int it = 0; it < 2; it++) {
            int idx = tid + it * 256;
            int m  = idx >> 2;
            int k8 = idx & 3;
            int gk = k0 + k8 * 8;
            bool kok = (gk < K);
            {
                int gm = m0 + m;
                const void* src = kok ? (const void*)(A + (size_t)gm * lda + gk)
                                      : (const void*)A;
                uint32_t dst = (uint32_t)__cvta_generic_to_shared(
                                    Asb + m * HSTRIDE + k8 * 8);
                cp_async16(dst, src, kok);
            }
            {
                int gn = n0 + m;
                bool ok = kok && (gn < N);
                const void* src = ok ? (const void*)(B + (size_t)gn * ldb + gk)
                                     : (const void*)B;
                uint32_t dst = (uint32_t)__cvta_generic_to_shared(
                                    Bsb + m * HSTRIDE + k8 * 8);
                cp_async16(dst, src, ok);
            }
        }
    };

    load_tiles(0, 0);
    cp_commit();

    for (int c = 0; c < nc; c++) {
        if (c + 1 < nc) load_tiles((c + 1) & 1, c + 1);
        cp_commit();
        cp_wait1();
        __syncthreads();

        uint32_t bufOff = (uint32_t)((c & 1) * TBUFH * 2);
        uint32_t aB = aBase + bufOff;
        uint32_t bB = bBase + bufOff;

        #pragma unroll
        for (int kk = 0; kk < 2; kk++) {
            uint32_t kOff = kk * 32;
            uint32_t af[4][4];
            #pragma unroll
            for (int mi = 0; mi < 4; mi++)
                ldsm_x4(aB + (uint32_t)(mi * 16 * 80) + kOff,
                        af[mi][0], af[mi][1], af[mi][2], af[mi][3]);
            uint32_t bf[4][2];
            #pragma unroll
            for (int p = 0; p < 2; p++)
                ldsm_x4(bB + (uint32_t)(p * 16 * 80) + kOff,
                        bf[2*p][0], bf[2*p][1], bf[2*p+1][0], bf[2*p+1][1]);
            #pragma unroll
            for (int mi = 0; mi < 4; mi++)
                #pragma unroll
                for (int ni = 0; ni < 4; ni++) {
                    asm volatile(
                        "mma.sync.aligned.m16n8k16.row.col.f32.bf16.bf16.f32 "
                        "{%0,%1,%2,%3}, {%4,%5,%6,%7}, {%8,%9}, {%0,%1,%2,%3};\n"
                        : "+f"(acc[mi][ni][0]), "+f"(acc[mi][ni][1]),
                          "+f"(acc[mi][ni][2]), "+f"(acc[mi][ni][3])
                        : "r"(af[mi][0]), "r"(af[mi][1]),
                          "r"(af[mi][2]), "r"(af[mi][3]),
                          "r"(bf[ni][0]), "r"(bf[ni][1]));
                }
        }
        __syncthreads();
    }

    // epilogue — paired (8B fp32 / 4B bf16) stores
    #pragma unroll
    for (int mi = 0; mi < 4; mi++) {
        int r0 = m0 + wm + mi * 16 + gid;
        #pragma unroll
        for (int ni = 0; ni < 4; ni++) {
            int col = n0 + wn + ni * 8 + tig * 2;
            if (col >= N) continue;
            #pragma unroll
            for (int half = 0; half < 2; half++) {
                int row = r0 + half * 8;
                if (row >= M) continue;
                float v0 = acc[mi][ni][half * 2 + 0];
                float v1 = acc[mi][ni][half * 2 + 1];
                if (epi == 1) {
                    v0 += bias[col];
                    v1 += bias[col + 1];
                    v0 = fmaxf(v0, 0.f) + log1pf(expf(-fabsf(v0)));
                    v1 = fmaxf(v1, 0.f) + log1pf(expf(-fabsf(v1)));
                } else if (epi == 2) {
                    float2 rv = *reinterpret_cast<const float2*>(
                                    resid + (size_t)row * ldr + col);
                    v0 += rv.x; v1 += rv.y;
                    *reinterpret_cast<float2*>(
                        C + (size_t)(row ^ (SEQL - 1)) * ldc + col)
                        = make_float2(v0, v1);
                    continue;
                }
                if (C)
                    *reinterpret_cast<float2*>(C + (size_t)row * ldc + col)
                        = make_float2(v0, v1);
                if (Cb)
                    *reinterpret_cast<__nv_bfloat162*>(
                        Cb + (size_t)row * ldc + col)
                        = __floats2bfloat162_rn(v0, v1);
            }
        }
    }
}

// ------- causal depthwise conv (k=4) + SiLU, bf16 input, x4 over d ----------
__global__ void conv_silu_kernel(const __nv_bfloat16* __restrict__ xzb,
                                 const float* __restrict__ w,
                                 const float* __restrict__ b,
                                 float* __restrict__ out,
                                 __nv_bfloat16* __restrict__ outb)
{
    int idx = blockIdx.x * blockDim.x + threadIdx.x;   // over NTOK*DI/4
    if (idx >= NTOK * (DI / 4)) return;
    int d4 = idx % (DI / 4);
    int r  = idx / (DI / 4);
    int d  = d4 * 4;
    int l  = r & (SEQL - 1);

    float4 acc = *reinterpret_cast<const float4*>(b + d);
    #pragma unroll
    for (int j = 0; j < 4; j++) {
        int li = l - 3 + j;
        if (li >= 0) {
            uint2 raw = *reinterpret_cast<const uint2*>(
                            xzb + (size_t)(r - 3 + j) * XZW + d);
            __nv_bfloat162 p0 = *reinterpret_cast<__nv_bfloat162*>(&raw.x);
            __nv_bfloat162 p1 = *reinterpret_cast<__nv_bfloat162*>(&raw.y);
            acc.x = fmaf(__bfloat162float(p0.x), w[(d + 0) * 4 + j], acc.x);
            acc.y = fmaf(__bfloat162float(p0.y), w[(d + 1) * 4 + j], acc.y);
            acc.z = fmaf(__bfloat162float(p1.x), w[(d + 2) * 4 + j], acc.z);
            acc.w = fmaf(__bfloat162float(p1.y), w[(d + 3) * 4 + j], acc.w);
        }
    }
    float4 v;
    v.x = acc.x / (1.f + __expf(-acc.x));
    v.y = acc.y / (1.f + __expf(-acc.y));
    v.z = acc.z / (1.f + __expf(-acc.z));
    v.w = acc.w / (1.f + __expf(-acc.w));
    *reinterpret_cast<float4*>(out + (size_t)r * DI + d) = v;
    __nv_bfloat162 b0 = __floats2bfloat162_rn(v.x, v.y);
    __nv_bfloat162 b1 = __floats2bfloat162_rn(v.z, v.w);
    uint2 pk = make_uint2(*(uint32_t*)&b0, *(uint32_t*)&b1);
    *reinterpret_cast<uint2*>(outb + (size_t)r * DI + d) = pk;
}

// ---------------- selective scan: 16 lanes per (b,d), B/C interleaved -------
__global__ void scan_kernel(const float* __restrict__ dt,
                            const float* __restrict__ xs,
                            const float* __restrict__ xdbl,
                            const float* __restrict__ A_log,
                            float* __restrict__ y)
{
    int b = blockIdx.y;
    int d = blockIdx.x * 16 + (threadIdx.x >> 4);
    int n = threadIdx.x & 15;

    float Adn = -__expf(A_log[d * DS + n]);

    size_t rbase = (size_t)b * SEQL;
    const float*  dtp = dt + rbase * DI + d;
    const float*  xsp = xs + rbase * DI + d;
    const float2* BCp = reinterpret_cast<const float2*>(
                            xdbl + rbase * XD + DTR) + n;   // {B_n, C_n}
    float*        yp  = y + rbase * DI + d;

    float h = 0.f;
    for (int l = 0; l < SEQL; l++) {
        float  dtv = __ldg(dtp); dtp += DI;
        float  xv  = __ldg(xsp); xsp += DI;
        float2 bc  = __ldg(BCp); BCp += XD / 2;
        float a = __expf(dtv * Adn);
        h = fmaf(a, h, dtv * xv * bc.x);
        float p = h * bc.y;
        p += __shfl_xor_sync(0xffffffffu, p, 8);
        p += __shfl_xor_sync(0xffffffffu, p, 4);
        p += __shfl_xor_sync(0xffffffffu, p, 2);
        p += __shfl_xor_sync(0xffffffffu, p, 1);
        if (n == 0) *yp = p;
        yp += DI;
    }
}

// ------- gate x4: yb = bf16((y + xsb*Dp) * silu(z)), xs/z from bf16 ---------
__global__ void gate_kernel(const float* __restrict__ y,
                            const __nv_bfloat16* __restrict__ xsb,
                            const __nv_bfloat16* __restrict__ xzb,
                            const float* __restrict__ Dp,
                            __nv_bfloat16* __restrict__ yb)
{
    int idx = blockIdx.x * blockDim.x + threadIdx.x;   // over NTOK*DI/4
    if (idx >= NTOK * (DI / 4)) return;
    int d4 = idx % (DI / 4);
    int r  = idx / (DI / 4);
    int d  = d4 * 4;

    float4 yv = *reinterpret_cast<const float4*>(y + (size_t)r * DI + d);
    uint2 xr = *reinterpret_cast<const uint2*>(xsb + (size_t)r * DI + d);
    uint2 zr = *reinterpret_cast<const uint2*>(xzb + (size_t)r * XZW + DI + d);
    float4 Dv = *reinterpret_cast<const float4*>(Dp + d);

    __nv_bfloat162 x0 = *reinterpret_cast<__nv_bfloat162*>(&xr.x);
    __nv_bfloat162 x1 = *reinterpret_cast<__nv_bfloat162*>(&xr.y);
    __nv_bfloat162 z0 = *reinterpret_cast<__nv_bfloat162*>(&zr.x);
    __nv_bfloat162 z1 = *reinterpret_cast<__nv_bfloat162*>(&zr.y);

    float zx = __bfloat162float(z0.x), zy = __bfloat162float(z0.y);
    float zz = __bfloat162float(z1.x), zw = __bfloat162float(z1.y);

    float4 o;
    o.x = fmaf(__bfloat162float(x0.x), Dv.x, yv.x) * (zx / (1.f + __expf(-zx)));
    o.y = fmaf(__bfloat162float(x0.y), Dv.y, yv.y) * (zy / (1.f + __expf(-zy)));
    o.z = fmaf(__bfloat162float(x1.x), Dv.z, yv.z) * (zz / (1.f + __expf(-zz)));
    o.w = fmaf(__bfloat162float(x1.y), Dv.w, yv.w) * (zw / (1.f + __expf(-zw)));

    __nv_bfloat162 b0 = __floats2bfloat162_rn(o.x, o.y);
    __nv_bfloat162 b1 = __floats2bfloat162_rn(o.z, o.w);
    uint2 pk = make_uint2(*(uint32_t*)&b0, *(uint32_t*)&b1);
    *reinterpret_cast<uint2*>(yb + (size_t)r * DI + d) = pk;
}

// ---------------- launcher ---------------------------------------------------
extern "C" void kernel_launch(void* const* d_in, const int* in_sizes, int n_in,
                              void* d_out, int out_size)
{
    const float* x        = (const float*)d_in[0];
    const float* norm_w   = (const float*)d_in[1];
    const float* norm_b   = (const float*)d_in[2];
    const float* in_proj  = (const float*)d_in[3];
    const float* conv_w   = (const float*)d_in[4];
    const float* conv_b   = (const float*)d_in[5];
    const float* x_proj   = (const float*)d_in[6];
    const float* dt_w     = (const float*)d_in[7];
    const float* dt_b     = (const float*)d_in[8];
    const float* A_log    = (const float*)d_in[9];
    const float* Dp       = (const float*)d_in[10];
    const float* out_proj = (const float*)d_in[11];

    float *xs, *xdbl, *dt, *y, *h2;
    __nv_bfloat16 *xzb, *xnb, *xsb, *xdblb, *yb, *w_inp, *w_xp, *w_dtw, *w_outp;
    cudaGetSymbolAddress((void**)&xs,    g_xs);
    cudaGetSymbolAddress((void**)&xdbl,  g_xdbl);
    cudaGetSymbolAddress((void**)&dt,    g_dt);
    cudaGetSymbolAddress((void**)&y,     g_y);
    cudaGetSymbolAddress((void**)&h2,    g_h2);
    cudaGetSymbolAddress((void**)&xzb,   g_xzb);
    cudaGetSymbolAddress((void**)&xnb,   g_xnb);
    cudaGetSymbolAddress((void**)&xsb,   g_xsb);
    cudaGetSymbolAddress((void**)&xdblb, g_xdblb);
    cudaGetSymbolAddress((void**)&yb,    g_yb);
    cudaGetSymbolAddress((void**)&w_inp, g_w_inp);
    cudaGetSymbolAddress((void**)&w_xp,  g_w_xp);
    cudaGetSymbolAddress((void**)&w_dtw, g_w_dtw);
    cudaGetSymbolAddress((void**)&w_outp,g_w_outp);

    const int SMEM_T = 4 * TBUFH * (int)sizeof(__nv_bfloat16);   // 40960 B
    static int attr_set = 0;
    if (!attr_set) {
        cudaFuncSetAttribute(gemm_bf16,
                             cudaFuncAttributeMaxDynamicSharedMemorySize, SMEM_T);
        attr_set = 1;
    }

    const int EW = 256;

    cvt4_kernel<<<((int)(W_INP  / 4) + EW - 1) / EW, EW>>>(
        (const float4*)in_proj,  (__nv_bfloat162*)w_inp,  (int)(W_INP  / 4));
    cvt_xp_kernel<<<((int)W_XP + EW - 1) / EW, EW>>>(x_proj, w_xp);
    cvt4_kernel<<<((int)(W_DTW  / 4) + EW - 1) / EW, EW>>>(
        (const float4*)dt_w,     (__nv_bfloat162*)w_dtw,  (int)(W_DTW  / 4));
    cvt4_kernel<<<((int)(W_OUTP / 4) + EW - 1) / EW, EW>>>(
        (const float4*)out_proj, (__nv_bfloat162*)w_outp, (int)(W_OUTP / 4));

    for (int i = 0; i < 2; i++) {
        const float* cur = (i == 0) ? x : h2;
        float* nxt = (i == 0) ? h2 : (float*)d_out;

        // 1. layernorm -> bf16 xn
        ln_kernel<<<NTOK, 128>>>(cur, norm_w + i * DM, norm_b + i * DM, xnb);

        // 2. xzb = bf16(xn @ in_proj^T)   (M=16384, N=1536, K=384)
        {
            dim3 g(XZW / TBN, NTOK / TBM);
            gemm_bf16<<<g, 256, SMEM_T>>>(xnb, DM,
                                          w_inp + (size_t)i * XZW * DM, DM,
                                          nullptr, XZW, xzb, nullptr, nullptr, 0,
                                          NTOK, XZW, DM, 0);
        }

        // 3. xs = silu(causal_conv(xzb[:, :768]))  (fp32 + bf16), x4
        conv_silu_kernel<<<(NTOK * (DI / 4) + EW - 1) / EW, EW>>>(
            xzb, conv_w + (size_t)i * DI * 4, conv_b + i * DI, xs, xsb);

        // 4. xdbl = xs @ x_projP^T  (rows permuted: dt, B0,C0,B1,C1,...)
        {
            dim3 g(1, NTOK / TBM);
            gemm_bf16<<<g, 256, SMEM_T>>>(xsb, DI,
                                          w_xp + (size_t)i * XD * DI, DI,
                                          xdbl, XD, xdblb, nullptr, nullptr, 0,
                                          NTOK, XD, DI, 0);
        }

        // 5. dt = softplus(xdbl[:, :24] @ dt_w^T + dt_b)  (N=768, K=24)
        {
            dim3 g(DI / TBN, NTOK / TBM);
            gemm_bf16<<<g, 256, SMEM_T>>>(xdblb, XD,
                                          w_dtw + (size_t)i * DI * DTR, DTR,
                                          dt, DI, nullptr, dt_b + i * DI,
                                          nullptr, 0,
                                          NTOK, DI, DTR, 1);
        }

        // 6. selective scan -> y (fp32)
        {
            dim3 g(DI / 16, NB);
            scan_kernel<<<g, 256>>>(dt, xs, xdbl,
                                    A_log + (size_t)i * DI * DS, y);
        }

        // 7. gate x4 -> bf16 yb (xs, z from bf16)
        gate_kernel<<<(NTOK * (DI / 4) + EW - 1) / EW, EW>>>(
            y, xsb, xzb, Dp + i * DI, yb);

        // 8. out = flip(yb @ out_proj^T + cur)  (N=384, K=768), flip fused
        {
            dim3 g(DM / TBN, NTOK / TBM);
            gemm_bf16<<<g, 256, SMEM_T>>>(yb, DI,
                                          w_outp + (size_t)i * DM * DI, DI,
                                          nxt, DM, nullptr, nullptr, cur, DM,
                                          NTOK, DM, DI, 2);
        }
    }
}

// round 17
// speedup vs baseline: 1.0285x; 1.0285x over previous
#include <cuda_runtime.h>
#include <cuda_bf16.h>
#include <math.h>
#include <stdint.h>

#define NTOK 16384          // BATCH * SEQ
#define SEQL 2048
#define NB   8
#define DM   384
#define DI   768
#define DS   16
#define DTR  24
#define XD   56             // DTR + 2*DS
#define XZW  1536           // 2*DI

// ---------------- scratch (static device memory; no allocation) ------------
__device__ __align__(16) float g_xs  [(size_t)NTOK * DI];
__device__ __align__(16) float g_xdbl[(size_t)NTOK * XD];
__device__ __align__(16) float g_dt  [(size_t)NTOK * DI];
__device__ __align__(16) float g_y   [(size_t)NTOK * DI];
__device__ __align__(16) float g_h2  [(size_t)NTOK * DM];

// bf16 tensors
__device__ __align__(16) __nv_bfloat16 g_xzb  [(size_t)NTOK * XZW];
__device__ __align__(16) __nv_bfloat16 g_xnb  [(size_t)NTOK * DM];
__device__ __align__(16) __nv_bfloat16 g_xsb  [(size_t)NTOK * DI];
__device__ __align__(16) __nv_bfloat16 g_xdblb[(size_t)NTOK * XD];
__device__ __align__(16) __nv_bfloat16 g_yb   [(size_t)NTOK * DI];
// bf16 weights
#define W_INP  ((size_t)2 * XZW * DM)
#define W_XP   ((size_t)2 * XD * DI)
#define W_DTW  ((size_t)2 * DI * DTR)
#define W_OUTP ((size_t)2 * DM * DI)
__device__ __align__(16) __nv_bfloat16 g_w_inp [W_INP];
__device__ __align__(16) __nv_bfloat16 g_w_xp  [W_XP];
__device__ __align__(16) __nv_bfloat16 g_w_dtw [W_DTW];
__device__ __align__(16) __nv_bfloat16 g_w_outp[W_OUTP];

// ---------------- fp32 -> bf16 conversion (vectorized) ----------------------
__global__ void cvt4_kernel(const float4* __restrict__ src,
                            __nv_bfloat162* __restrict__ dst, int n4)
{
    int i = blockIdx.x * blockDim.x + threadIdx.x;
    if (i >= n4) return;
    float4 v = src[i];
    dst[2 * i + 0] = __floats2bfloat162_rn(v.x, v.y);
    dst[2 * i + 1] = __floats2bfloat162_rn(v.z, v.w);
}

// ------- x_proj cvt with B/C row interleave ---------------------------------
__global__ void cvt_xp_kernel(const float* __restrict__ src,
                              __nv_bfloat16* __restrict__ dst)
{
    int i = blockIdx.x * blockDim.x + threadIdx.x;   // over 2*XD*DI
    if (i >= 2 * XD * DI) return;
    int layer = i / (XD * DI);
    int rem   = i - layer * XD * DI;
    int row   = rem / DI;
    int col   = rem - row * DI;
    int srow;
    if (row < DTR)             srow = row;
    else {
        int t = row - DTR;     // 0..31
        srow = (t & 1) ? (DTR + DS + (t >> 1)) : (DTR + (t >> 1));
    }
    dst[i] = __float2bfloat16_rn(src[(size_t)layer * XD * DI
                                     + (size_t)srow * DI + col]);
}

// ---------------- layernorm: one block per token, bf16 output --------------
__global__ void ln_kernel(const float* __restrict__ in,
                          const float* __restrict__ w,
                          const float* __restrict__ b,
                          __nv_bfloat16* __restrict__ out)
{
    int row = blockIdx.x;
    const float* x = in + (size_t)row * DM;
    int t = threadIdx.x;
    float v[3];
    float s = 0.f;
    #pragma unroll
    for (int i = 0; i < 3; i++) { v[i] = x[t + i * 128]; s += v[i]; }

    __shared__ float red[4];
    #pragma unroll
    for (int o = 16; o > 0; o >>= 1) s += __shfl_xor_sync(0xffffffffu, s, o);
    if ((t & 31) == 0) red[t >> 5] = s;
    __syncthreads();
    float mu = (red[0] + red[1] + red[2] + red[3]) * (1.f / 384.f);

    float q = 0.f;
    #pragma unroll
    for (int i = 0; i < 3; i++) { float d = v[i] - mu; q = fmaf(d, d, q); }
    #pragma unroll
    for (int o = 16; o > 0; o >>= 1) q += __shfl_xor_sync(0xffffffffu, q, o);
    __syncthreads();
    if ((t & 31) == 0) red[t >> 5] = q;
    __syncthreads();
    float var = (red[0] + red[1] + red[2] + red[3]) * (1.f / 384.f);
    float rs = rsqrtf(var + 1e-5f);

    __nv_bfloat16* o = out + (size_t)row * DM;
    #pragma unroll
    for (int i = 0; i < 3; i++) {
        int c = t + i * 128;
        o[c] = __float2bfloat16_rn((v[i] - mu) * rs * w[c] + b[c]);
    }
}

// ================= BF16 tensor-core NT GEMM (ldmatrix mainloop) =============
#define TBM 128
#define TBN 128
#define TBK 32
#define HSTRIDE 40
#define TBUFH (TBM * HSTRIDE)

__device__ __forceinline__ void cp_async16(uint32_t dst, const void* src, bool ok)
{
    int sz = ok ? 16 : 0;
    asm volatile("cp.async.cg.shared.global [%0], [%1], 16, %2;\n"
                 :: "r"(dst), "l"(src), "r"(sz));
}
__device__ __forceinline__ void cp_commit() {
    asm volatile("cp.async.commit_group;\n");
}
__device__ __forceinline__ void cp_wait1() {
    asm volatile("cp.async.wait_group 1;\n");
}
__device__ __forceinline__ void ldsm_x4(uint32_t addr, uint32_t& r0, uint32_t& r1,
                                        uint32_t& r2, uint32_t& r3)
{
    asm volatile("ldmatrix.sync.aligned.m8n8.x4.shared.b16 {%0,%1,%2,%3}, [%4];\n"
                 : "=r"(r0), "=r"(r1), "=r"(r2), "=r"(r3) : "r"(addr));
}

// epi: 0 = none, 1 = softplus(v + bias[n]),
//      2 = v + resid[m*ldr+n], stored with sequence flip (row ^ 2047)
__global__ void __launch_bounds__(256, 2)
gemm_bf16(const __nv_bfloat16* __restrict__ A, int lda,
          const __nv_bfloat16* __restrict__ B, int ldb,
          float* __restrict__ C, int ldc,
          __nv_bfloat16* __restrict__ Cb,
          const float* __restrict__ bias,
          const float* __restrict__ resid, int ldr,
          int M, int N, int K, int epi)
{
    extern __shared__ __nv_bfloat16 smem[];
    __nv_bfloat16* AsB = smem;
    __nv_bfloat16* BsB = smem + 2 * TBUFH;

    int tid  = threadIdx.x;
    int lane = tid & 31;
    int warp = tid >> 5;
    int gid  = lane >> 2;
    int tig  = lane & 3;
    int wm   = (warp >> 2) * 64;
    int wn   = (warp & 3) * 32;

    int m0 = blockIdx.y * TBM;
    int n0 = blockIdx.x * TBN;
    int nc = (K + TBK - 1) / TBK;

    uint32_t smem_u = (uint32_t)__cvta_generic_to_shared(smem);

    int ar = lane & 15, ahi = lane >> 4;
    uint32_t aBase = smem_u + (uint32_t)((wm + ar) * 80 + ahi * 16);
    int bq = lane >> 3;
    uint32_t bBase = smem_u + (uint32_t)(2 * TBUFH * 2)
                   + (uint32_t)((wn + (bq >> 1) * 8 + (lane & 7)) * 80
                                + (bq & 1) * 16);

    float acc[4][4][4];
    #pragma unroll
    for (int i = 0; i < 4; i++)
        #pragma unroll
        for (int j = 0; j < 4; j++)
            #pragma unroll
            for (int c = 0; c < 4; c++) acc[i][j][c] = 0.f;

    auto load_tiles = [&](int buf, int chunk) {
        int k0 = chunk * TBK;
        __nv_bfloat16* Asb = AsB + buf * TBUFH;
        __nv_bfloat16* Bsb = BsB + buf * TBUFH;
        #pragma unroll
        for (int it = 0; it < 2; it++) {
            int idx = tid + it * 256;
            int m  = idx >> 2;
            int k8 = idx & 3;
            int gk = k0 + k8 * 8;
            bool kok = (gk < K);
            {
                int gm = m0 + m;
                const void* src = kok ? (const void*)(A + (size_t)gm * lda + gk)
                                      : (const void*)A;
                uint32_t dst = (uint32_t)__cvta_generic_to_shared(
                                    Asb + m * HSTRIDE + k8 * 8);
                cp_async16(dst, src, kok);
            }
            {
                int gn = n0 + m;
                bool ok = kok && (gn < N);
                const void* src = ok ? (const void*)(B + (size_t)gn * ldb + gk)
                                     : (const void*)B;
                uint32_t dst = (uint32_t)__cvta_generic_to_shared(
                                    Bsb + m * HSTRIDE + k8 * 8);
                cp_async16(dst, src, ok);
            }
        }
    };

    load_tiles(0, 0);
    cp_commit();

    for (int c = 0; c < nc; c++) {
        if (c + 1 < nc) load_tiles((c + 1) & 1, c + 1);
        cp_commit();
        cp_wait1();
        __syncthreads();

        uint32_t bufOff = (uint32_t)((c & 1) * TBUFH * 2);
        uint32_t aB = aBase + bufOff;
        uint32_t bB = bBase + bufOff;

        #pragma unroll
        for (int kk = 0; kk < 2; kk++) {
            uint32_t kOff = kk * 32;
            uint32_t af[4][4];
            #pragma unroll
            for (int mi = 0; mi < 4; mi++)
                ldsm_x4(aB + (uint32_t)(mi * 16 * 80) + kOff,
                        af[mi][0], af[mi][1], af[mi][2], af[mi][3]);
            uint32_t bf[4][2];
            #pragma unroll
            for (int p = 0; p < 2; p++)
                ldsm_x4(bB + (uint32_t)(p * 16 * 80) + kOff,
                        bf[2*p][0], bf[2*p][1], bf[2*p+1][0], bf[2*p+1][1]);
            #pragma unroll
            for (int mi = 0; mi < 4; mi++)
                #pragma unroll
                for (int ni = 0; ni < 4; ni++) {
                    asm volatile(
                        "mma.sync.aligned.m16n8k16.row.col.f32.bf16.bf16.f32 "
                        "{%0,%1,%2,%3}, {%4,%5,%6,%7}, {%8,%9}, {%0,%1,%2,%3};\n"
                        : "+f"(acc[mi][ni][0]), "+f"(acc[mi][ni][1]),
                          "+f"(acc[mi][ni][2]), "+f"(acc[mi][ni][3])
                        : "r"(af[mi][0]), "r"(af[mi][1]),
                          "r"(af[mi][2]), "r"(af[mi][3]),
                          "r"(bf[ni][0]), "r"(bf[ni][1]));
                }
        }
        __syncthreads();
    }

    // epilogue — paired (8B fp32 / 4B bf16) stores
    #pragma unroll
    for (int mi = 0; mi < 4; mi++) {
        int r0 = m0 + wm + mi * 16 + gid;
        #pragma unroll
        for (int ni = 0; ni < 4; ni++) {
            int col = n0 + wn + ni * 8 + tig * 2;
            if (col >= N) continue;
            #pragma unroll
            for (int half = 0; half < 2; half++) {
                int row = r0 + half * 8;
                if (row >= M) continue;
                float v0 = acc[mi][ni][half * 2 + 0];
                float v1 = acc[mi][ni][half * 2 + 1];
                if (epi == 1) {
                    v0 += bias[col];
                    v1 += bias[col + 1];
                    v0 = fmaxf(v0, 0.f) + log1pf(expf(-fabsf(v0)));
                    v1 = fmaxf(v1, 0.f) + log1pf(expf(-fabsf(v1)));
                } else if (epi == 2) {
                    float2 rv = *reinterpret_cast<const float2*>(
                                    resid + (size_t)row * ldr + col);
                    v0 += rv.x; v1 += rv.y;
                    *reinterpret_cast<float2*>(
                        C + (size_t)(row ^ (SEQL - 1)) * ldc + col)
                        = make_float2(v0, v1);
                    continue;
                }
                if (C)
                    *reinterpret_cast<float2*>(C + (size_t)row * ldc + col)
                        = make_float2(v0, v1);
                if (Cb)
                    *reinterpret_cast<__nv_bfloat162*>(
                        Cb + (size_t)row * ldc + col)
                        = __floats2bfloat162_rn(v0, v1);
            }
        }
    }
}

// ---------------- causal depthwise conv (k=4) + SiLU, bf16 input ------------
__global__ void conv_silu_kernel(const __nv_bfloat16* __restrict__ xzb,
                                 const float* __restrict__ w,
                                 const float* __restrict__ b,
                                 float* __restrict__ out,
                                 __nv_bfloat16* __restrict__ outb)
{
    int idx = blockIdx.x * blockDim.x + threadIdx.x;
    if (idx >= NTOK * DI) return;
    int d = idx % DI;
    int r = idx / DI;
    int l = r & (SEQL - 1);
    float acc = b[d];
    const float* wd = w + d * 4;
    #pragma unroll
    for (int j = 0; j < 4; j++) {
        int li = l - 3 + j;
        if (li >= 0)
            acc = fmaf(__bfloat162float(xzb[(size_t)(r - 3 + j) * XZW + d]),
                       wd[j], acc);
    }
    float v = acc / (1.f + __expf(-acc));   // silu
    out[idx] = v;
    outb[idx] = __float2bfloat16_rn(v);
}

// ---------------- selective scan: 16 lanes per (b,d), B/C interleaved -------
__global__ void scan_kernel(const float* __restrict__ dt,
                            const float* __restrict__ xs,
                            const float* __restrict__ xdbl,
                            const float* __restrict__ A_log,
                            float* __restrict__ y)
{
    int b = blockIdx.y;
    int d = blockIdx.x * 16 + (threadIdx.x >> 4);
    int n = threadIdx.x & 15;

    float Adn = -__expf(A_log[d * DS + n]);

    size_t rbase = (size_t)b * SEQL;
    const float*  dtp = dt + rbase * DI + d;
    const float*  xsp = xs + rbase * DI + d;
    const float2* BCp = reinterpret_cast<const float2*>(
                            xdbl + rbase * XD + DTR) + n;   // {B_n, C_n}
    float*        yp  = y + rbase * DI + d;

    float h = 0.f;
    for (int l = 0; l < SEQL; l++) {
        float  dtv = __ldg(dtp); dtp += DI;
        float  xv  = __ldg(xsp); xsp += DI;
        float2 bc  = __ldg(BCp); BCp += XD / 2;
        float a = __expf(dtv * Adn);
        h = fmaf(a, h, dtv * xv * bc.x);
        float p = h * bc.y;
        p += __shfl_xor_sync(0xffffffffu, p, 8);
        p += __shfl_xor_sync(0xffffffffu, p, 4);
        p += __shfl_xor_sync(0xffffffffu, p, 2);
        p += __shfl_xor_sync(0xffffffffu, p, 1);
        if (n == 0) *yp = p;
        yp += DI;
    }
}

// ---- gate (scalar): yb = bf16((y + xsb*Dp) * silu(z)), xs/z from bf16 ------
__global__ void gate_kernel(const float* __restrict__ y,
                            const __nv_bfloat16* __restrict__ xsb,
                            const __nv_bfloat16* __restrict__ xzb,
                            const float* __restrict__ Dp,
                            __nv_bfloat16* __restrict__ yb)
{
    int idx = blockIdx.x * blockDim.x + threadIdx.x;
    if (idx >= NTOK * DI) return;
    int d = idx % DI;
    int r = idx / DI;
    float z = __bfloat162float(xzb[(size_t)r * XZW + DI + d]);
    float s = z / (1.f + __expf(-z));
    float xv = __bfloat162float(xsb[idx]);
    yb[idx] = __float2bfloat16_rn(fmaf(xv, Dp[d], y[idx]) * s);
}

// ---------------- launcher ---------------------------------------------------
extern "C" void kernel_launch(void* const* d_in, const int* in_sizes, int n_in,
                              void* d_out, int out_size)
{
    const float* x        = (const float*)d_in[0];
    const float* norm_w   = (const float*)d_in[1];
    const float* norm_b   = (const float*)d_in[2];
    const float* in_proj  = (const float*)d_in[3];
    const float* conv_w   = (const float*)d_in[4];
    const float* conv_b   = (const float*)d_in[5];
    const float* x_proj   = (const float*)d_in[6];
    const float* dt_w     = (const float*)d_in[7];
    const float* dt_b     = (const float*)d_in[8];
    const float* A_log    = (const float*)d_in[9];
    const float* Dp       = (const float*)d_in[10];
    const float* out_proj = (const float*)d_in[11];

    float *xs, *xdbl, *dt, *y, *h2;
    __nv_bfloat16 *xzb, *xnb, *xsb, *xdblb, *yb, *w_inp, *w_xp, *w_dtw, *w_outp;
    cudaGetSymbolAddress((void**)&xs,    g_xs);
    cudaGetSymbolAddress((void**)&xdbl,  g_xdbl);
    cudaGetSymbolAddress((void**)&dt,    g_dt);
    cudaGetSymbolAddress((void**)&y,     g_y);
    cudaGetSymbolAddress((void**)&h2,    g_h2);
    cudaGetSymbolAddress((void**)&xzb,   g_xzb);
    cudaGetSymbolAddress((void**)&xnb,   g_xnb);
    cudaGetSymbolAddress((void**)&xsb,   g_xsb);
    cudaGetSymbolAddress((void**)&xdblb, g_xdblb);
    cudaGetSymbolAddress((void**)&yb,    g_yb);
    cudaGetSymbolAddress((void**)&w_inp, g_w_inp);
    cudaGetSymbolAddress((void**)&w_xp,  g_w_xp);
    cudaGetSymbolAddress((void**)&w_dtw, g_w_dtw);
    cudaGetSymbolAddress((void**)&w_outp,g_w_outp);

    const int SMEM_T = 4 * TBUFH * (int)sizeof(__nv_bfloat16);   // 40960 B
    static int attr_set = 0;
    if (!attr_set) {
        cudaFuncSetAttribute(gemm_bf16,
                             cudaFuncAttributeMaxDynamicSharedMemorySize, SMEM_T);
        attr_set = 1;
    }

    const int EW = 256;

    cvt4_kernel<<<((int)(W_INP  / 4) + EW - 1) / EW, EW>>>(
        (const float4*)in_proj,  (__nv_bfloat162*)w_inp,  (int)(W_INP  / 4));
    cvt_xp_kernel<<<((int)W_XP + EW - 1) / EW, EW>>>(x_proj, w_xp);
    cvt4_kernel<<<((int)(W_DTW  / 4) + EW - 1) / EW, EW>>>(
        (const float4*)dt_w,     (__nv_bfloat162*)w_dtw,  (int)(W_DTW  / 4));
    cvt4_kernel<<<((int)(W_OUTP / 4) + EW - 1) / EW, EW>>>(
        (const float4*)out_proj, (__nv_bfloat162*)w_outp, (int)(W_OUTP / 4));

    for (int i = 0; i < 2; i++) {
        const float* cur = (i == 0) ? x : h2;
        float* nxt = (i == 0) ? h2 : (float*)d_out;

        // 1. layernorm -> bf16 xn
        ln_kernel<<<NTOK, 128>>>(cur, norm_w + i * DM, norm_b + i * DM, xnb);

        // 2. xzb = bf16(xn @ in_proj^T)   (M=16384, N=1536, K=384)
        {
            dim3 g(XZW / TBN, NTOK / TBM);
            gemm_bf16<<<g, 256, SMEM_T>>>(xnb, DM,
                                          w_inp + (size_t)i * XZW * DM, DM,
                                          nullptr, XZW, xzb, nullptr, nullptr, 0,
                                          NTOK, XZW, DM, 0);
        }

        // 3. xs = silu(causal_conv(xzb[:, :768]))  (fp32 + bf16)
        conv_silu_kernel<<<(NTOK * DI + EW - 1) / EW, EW>>>(
            xzb, conv_w + (size_t)i * DI * 4, conv_b + i * DI, xs, xsb);

        // 4. xdbl = xs @ x_projP^T  (rows permuted: dt, B0,C0,B1,C1,...)
        {
            dim3 g(1, NTOK / TBM);
            gemm_bf16<<<g, 256, SMEM_T>>>(xsb, DI,
                                          w_xp + (size_t)i * XD * DI, DI,
                                          xdbl, XD, xdblb, nullptr, nullptr, 0,
                                          NTOK, XD, DI, 0);
        }

        // 5. dt = softplus(xdbl[:, :24] @ dt_w^T + dt_b)  (N=768, K=24)
        {
            dim3 g(DI / TBN, NTOK / TBM);
            gemm_bf16<<<g, 256, SMEM_T>>>(xdblb, XD,
                                          w_dtw + (size_t)i * DI * DTR, DTR,
                                          dt, DI, nullptr, dt_b + i * DI,
                                          nullptr, 0,
                                          NTOK, DI, DTR, 1);
        }

        // 6. selective scan -> y (fp32)
        {
            dim3 g(DI / 16, NB);
            scan_kernel<<<g, 256>>>(dt, xs, xdbl,
                                    A_log + (size_t)i * DI * DS, y);
        }

        // 7. gate -> bf16 yb (xs, z from bf16)
        gate_kernel<<<(NTOK * DI + EW - 1) / EW, EW>>>(y, xsb, xzb,
                                                       Dp + i * DI, yb);

        // 8. out = flip(yb @ out_proj^T + cur)  (N=384, K=768), flip fused
        {
            dim3 g(DM / TBN, NTOK / TBM);
            gemm_bf16<<<g, 256, SMEM_T>>>(yb, DI,
                                          w_outp + (size_t)i * DM * DI, DI,
                                          nxt, DM, nullptr, nullptr, cur, DM,
                                          NTOK, DM, DI, 2);
        }
    }
}